// round 7
// baseline (speedup 1.0000x reference)
#include <cuda_runtime.h>
#include <cstdint>
#include <cstddef>

// ---------------------------------------------------------------------------
// Bottleneck: BN -> conv1x1(1024->256) -> relu -> BN -> conv1x1(256->64)
//             -> split (mu, logvar)
// B=32, C=1024, T=2048. BN folded into GEMM weights. GEMMs in tf32 mma.sync.
// ---------------------------------------------------------------------------

#define EPSV 1e-5f
constexpr int Tdim = 2048;
constexpr int Bn   = 32;
constexpr int BN   = 128;   // t-tile
constexpr int BK   = 16;    // k-tile

// scratch (allocation-free rule: __device__ globals)
__device__ float g_h[(size_t)Bn * 256 * Tdim];       // 64 MiB intermediate
__device__ float g_s1[1024], g_t1[1024];
__device__ float g_w1f[256 * 1024];
__device__ float g_b1f[256];
__device__ float g_s2[256], g_t2[256];
__device__ float g_w2f[64 * 256];
__device__ float g_b2f[64];

__device__ __forceinline__ float to_tf32(float v) {
    uint32_t u;
    asm("cvt.rna.tf32.f32 %0, %1;" : "=r"(u) : "f"(v));
    return __uint_as_float(u);
}

__device__ __forceinline__ void mma8(float* c, const uint32_t* a, const uint32_t* b) {
    asm volatile(
        "mma.sync.aligned.m16n8k8.row.col.f32.tf32.tf32.f32 "
        "{%0,%1,%2,%3}, {%4,%5,%6,%7}, {%8,%9}, {%0,%1,%2,%3};"
        : "+f"(c[0]), "+f"(c[1]), "+f"(c[2]), "+f"(c[3])
        : "r"(a[0]), "r"(a[1]), "r"(a[2]), "r"(a[3]), "r"(b[0]), "r"(b[1]));
}

// ---------------------------------------------------------------------------
// Per-channel BN stats over (B, T): emits scale s = g*rsqrt(var+eps),
// shift t = b - mean*s.  x layout: [B][C][T].  grid = C blocks, 256 threads.
// ---------------------------------------------------------------------------
__global__ void bn_stats_kernel(const float* __restrict__ x,
                                const float* __restrict__ gamma,
                                const float* __restrict__ beta,
                                float* __restrict__ s_out,
                                float* __restrict__ t_out,
                                int C)
{
    const int c = blockIdx.x, tid = threadIdx.x;
    float s = 0.f, ss = 0.f;
    const size_t cstride = (size_t)C * Tdim;
    const float* base = x + (size_t)c * Tdim;
    for (int b = 0; b < Bn; ++b) {
        const float4* row = reinterpret_cast<const float4*>(base + (size_t)b * cstride);
#pragma unroll
        for (int i = 0; i < (Tdim / 4) / 256; ++i) {
            float4 v = row[tid + i * 256];
            s  += (v.x + v.y) + (v.z + v.w);
            ss += (v.x * v.x + v.y * v.y) + (v.z * v.z + v.w * v.w);
        }
    }
#pragma unroll
    for (int o = 16; o > 0; o >>= 1) {
        s  += __shfl_xor_sync(0xffffffffu, s, o);
        ss += __shfl_xor_sync(0xffffffffu, ss, o);
    }
    __shared__ float rs[8], rss[8];
    if ((tid & 31) == 0) { rs[tid >> 5] = s; rss[tid >> 5] = ss; }
    __syncthreads();
    if (tid == 0) {
        float S = 0.f, SS = 0.f;
#pragma unroll
        for (int i = 0; i < 8; ++i) { S += rs[i]; SS += rss[i]; }
        const float invN = 1.0f / (float)(Bn * Tdim);
        float mean = S * invN;
        float var  = SS * invN - mean * mean;
        float sc   = gamma[c] * rsqrtf(var + EPSV);
        s_out[c] = sc;
        t_out[c] = beta[c] - mean * sc;
    }
}

// ---------------------------------------------------------------------------
// Fold BN into weights: wf[o,c] = w[o,c]*s[c];  bf[o] = bias[o] + sum_c w[o,c]*t[c]
// grid = M blocks (one output channel each), 256 threads.
// ---------------------------------------------------------------------------
__global__ void fold_kernel(const float* __restrict__ w,
                            const float* __restrict__ bias_in,
                            const float* __restrict__ s,
                            const float* __restrict__ t,
                            float* __restrict__ wf,
                            float* __restrict__ bf,
                            int K)
{
    const int o = blockIdx.x, tid = threadIdx.x;
    float part = 0.f;
    for (int c = tid; c < K; c += 256) {
        float wv = w[(size_t)o * K + c];
        wf[(size_t)o * K + c] = wv * s[c];
        part += wv * t[c];
    }
#pragma unroll
    for (int off = 16; off > 0; off >>= 1)
        part += __shfl_xor_sync(0xffffffffu, part, off);
    __shared__ float red[8];
    if ((tid & 31) == 0) red[tid >> 5] = part;
    __syncthreads();
    if (tid == 0) {
        float tot = 0.f;
#pragma unroll
        for (int i = 0; i < 8; ++i) tot += red[i];
        bf[o] = bias_in[o] + tot;
    }
}

// ---------------------------------------------------------------------------
// tf32 GEMM:  Out(row o, col t) = sum_k A[o,k] * X[b,k,t]  (+ bias, epilogue)
// Block tile BM x 128, BK=16, 8 warps (2x4), warp tile (BM/2) x 32.
// mma.sync m16n8k8.  A staged k-major in SMEM (conflict-free frag loads).
// EPI=0: relu, write h[b][o][t].  EPI=1: bias, scatter mu/logvar.
// ---------------------------------------------------------------------------
template <int BM, int MT, int EPI>
__global__ __launch_bounds__(256)
void gemm_tf32_kernel(const float* __restrict__ A,
                      const float* __restrict__ X,
                      const float* __restrict__ bias,
                      float* __restrict__ Out,
                      int K, int Mtot)
{
    constexpr int NT  = 4;
    constexpr int AP  = BM + 4;
    constexpr int BP  = BN + 4;
    constexpr int AF4 = (BM * BK) / (4 * 256);

    __shared__ float As[2][BK][AP];   // k-major: As[k][m]
    __shared__ float Bs[2][BK][BP];   // Bs[k][n]

    const int tid  = threadIdx.x;
    const int wid  = tid >> 5, lane = tid & 31;
    const int wrow = wid >> 2, wcol = wid & 3;      // 2 x 4 warp grid
    const int gid  = lane >> 2, tig = lane & 3;

    const int b  = blockIdx.z;
    const int t0 = blockIdx.x * BN;
    const int m0 = blockIdx.y * BM;

    const float* Xb = X + (size_t)b * K * Tdim;

    float acc[MT][NT][4];
#pragma unroll
    for (int i = 0; i < MT; ++i)
#pragma unroll
        for (int j = 0; j < NT; ++j)
#pragma unroll
            for (int e = 0; e < 4; ++e) acc[i][j][e] = 0.f;

    // global->smem mapping
    int ar[AF4], aj[AF4];
#pragma unroll
    for (int i = 0; i < AF4; ++i) {
        int id = tid + i * 256;
        ar[i] = id >> 2;          // row in A tile
        aj[i] = (id & 3) * 4;     // k offset (float4)
    }
    const int bkb = tid >> 5;           // B tile k row (then +8 for second)
    const int bnn = (lane) * 4;         // 32 lanes * 4 floats = full 128 row

    // ---- prologue: tile 0 ----
    {
#pragma unroll
        for (int i = 0; i < AF4; ++i) {
            float4 v = *reinterpret_cast<const float4*>(A + (size_t)(m0 + ar[i]) * K + aj[i]);
            As[0][aj[i] + 0][ar[i]] = to_tf32(v.x);
            As[0][aj[i] + 1][ar[i]] = to_tf32(v.y);
            As[0][aj[i] + 2][ar[i]] = to_tf32(v.z);
            As[0][aj[i] + 3][ar[i]] = to_tf32(v.w);
        }
#pragma unroll
        for (int i = 0; i < 2; ++i) {
            int k = bkb + i * 8;
            float4 v = *reinterpret_cast<const float4*>(Xb + (size_t)k * Tdim + t0 + bnn);
            float4 c4 = make_float4(to_tf32(v.x), to_tf32(v.y), to_tf32(v.z), to_tf32(v.w));
            *reinterpret_cast<float4*>(&Bs[0][k][bnn]) = c4;
        }
    }
    __syncthreads();

    const int KT = K / BK;
    float4 a_reg[AF4], b_reg[2];

    for (int kt = 0; kt < KT; ++kt) {
        const int cur = kt & 1;
        const bool has_next = (kt + 1 < KT);
        if (has_next) {
            const int k0 = (kt + 1) * BK;
#pragma unroll
            for (int i = 0; i < AF4; ++i)
                a_reg[i] = *reinterpret_cast<const float4*>(
                    A + (size_t)(m0 + ar[i]) * K + k0 + aj[i]);
#pragma unroll
            for (int i = 0; i < 2; ++i) {
                int k = bkb + i * 8;
                b_reg[i] = *reinterpret_cast<const float4*>(
                    Xb + (size_t)(k0 + k) * Tdim + t0 + bnn);
            }
        }

#pragma unroll
        for (int kc = 0; kc < 2; ++kc) {
            const int kk = kc * 8 + tig;
            uint32_t af[MT][4], bfr[NT][2];
#pragma unroll
            for (int mt = 0; mt < MT; ++mt) {
                const int r = wrow * (BM / 2) + mt * 16 + gid;
                af[mt][0] = __float_as_uint(As[cur][kk    ][r]);
                af[mt][1] = __float_as_uint(As[cur][kk    ][r + 8]);
                af[mt][2] = __float_as_uint(As[cur][kk + 4][r]);
                af[mt][3] = __float_as_uint(As[cur][kk + 4][r + 8]);
            }
#pragma unroll
            for (int nt = 0; nt < NT; ++nt) {
                const int cc = wcol * 32 + nt * 8 + gid;
                bfr[nt][0] = __float_as_uint(Bs[cur][kk    ][cc]);
                bfr[nt][1] = __float_as_uint(Bs[cur][kk + 4][cc]);
            }
#pragma unroll
            for (int mt = 0; mt < MT; ++mt)
#pragma unroll
                for (int nt = 0; nt < NT; ++nt)
                    mma8(acc[mt][nt], af[mt], bfr[nt]);
        }

        if (has_next) {
            const int nb = cur ^ 1;
#pragma unroll
            for (int i = 0; i < AF4; ++i) {
                As[nb][aj[i] + 0][ar[i]] = to_tf32(a_reg[i].x);
                As[nb][aj[i] + 1][ar[i]] = to_tf32(a_reg[i].y);
                As[nb][aj[i] + 2][ar[i]] = to_tf32(a_reg[i].z);
                As[nb][aj[i] + 3][ar[i]] = to_tf32(a_reg[i].w);
            }
#pragma unroll
            for (int i = 0; i < 2; ++i) {
                int k = bkb + i * 8;
                float4 c4 = make_float4(to_tf32(b_reg[i].x), to_tf32(b_reg[i].y),
                                        to_tf32(b_reg[i].z), to_tf32(b_reg[i].w));
                *reinterpret_cast<float4*>(&Bs[nb][k][bnn]) = c4;
            }
        }
        __syncthreads();
    }

    // ---- epilogue ----
#pragma unroll
    for (int mt = 0; mt < MT; ++mt) {
        const int row = m0 + wrow * (BM / 2) + mt * 16 + gid;
        const float bz0 = bias[row];
        const float bz1 = bias[row + 8];
#pragma unroll
        for (int nt = 0; nt < NT; ++nt) {
            const int col = t0 + wcol * 32 + nt * 8 + tig * 2;
            if constexpr (EPI == 0) {
                float* H = Out + ((size_t)b * Mtot + row) * Tdim + col;
                float2 v0 = make_float2(fmaxf(acc[mt][nt][0] + bz0, 0.f),
                                        fmaxf(acc[mt][nt][1] + bz0, 0.f));
                float2 v1 = make_float2(fmaxf(acc[mt][nt][2] + bz1, 0.f),
                                        fmaxf(acc[mt][nt][3] + bz1, 0.f));
                *reinterpret_cast<float2*>(H) = v0;
                *reinterpret_cast<float2*>(H + (size_t)8 * Tdim) = v1;
            } else {
                // out[b, o, t] -> mu (o<32) then logvar (o>=32), each flattened
                const int row1 = row + 8;
                size_t i0 = (row < 32)
                    ? ((size_t)b * 65536 + (size_t)row * Tdim)
                    : (2097152 + (size_t)b * 65536 + (size_t)(row - 32) * Tdim);
                size_t i1 = (row1 < 32)
                    ? ((size_t)b * 65536 + (size_t)row1 * Tdim)
                    : (2097152 + (size_t)b * 65536 + (size_t)(row1 - 32) * Tdim);
                float2 v0 = make_float2(acc[mt][nt][0] + bz0, acc[mt][nt][1] + bz0);
                float2 v1 = make_float2(acc[mt][nt][2] + bz1, acc[mt][nt][3] + bz1);
                *reinterpret_cast<float2*>(Out + i0 + col) = v0;
                *reinterpret_cast<float2*>(Out + i1 + col) = v1;
            }
        }
    }
}

// ---------------------------------------------------------------------------
extern "C" void kernel_launch(void* const* d_in, const int* in_sizes, int n_in,
                              void* d_out, int out_size)
{
    const float* x     = (const float*)d_in[0];
    const float* bn1_g = (const float*)d_in[1];
    const float* bn1_b = (const float*)d_in[2];
    const float* w1    = (const float*)d_in[3];
    const float* b1    = (const float*)d_in[4];
    const float* bn2_g = (const float*)d_in[5];
    const float* bn2_b = (const float*)d_in[6];
    const float* w2    = (const float*)d_in[7];
    const float* b2    = (const float*)d_in[8];
    float* out = (float*)d_out;

    float *h, *s1, *t1, *w1f, *b1f, *s2, *t2, *w2f, *b2f;
    cudaGetSymbolAddress((void**)&h,   g_h);
    cudaGetSymbolAddress((void**)&s1,  g_s1);
    cudaGetSymbolAddress((void**)&t1,  g_t1);
    cudaGetSymbolAddress((void**)&w1f, g_w1f);
    cudaGetSymbolAddress((void**)&b1f, g_b1f);
    cudaGetSymbolAddress((void**)&s2,  g_s2);
    cudaGetSymbolAddress((void**)&t2,  g_t2);
    cudaGetSymbolAddress((void**)&w2f, g_w2f);
    cudaGetSymbolAddress((void**)&b2f, g_b2f);

    // BN1 stats -> fold into W1 -> GEMM1(relu) -> h
    bn_stats_kernel<<<1024, 256>>>(x, bn1_g, bn1_b, s1, t1, 1024);
    fold_kernel<<<256, 256>>>(w1, b1, s1, t1, w1f, b1f, 1024);
    gemm_tf32_kernel<128, 4, 0><<<dim3(16, 2, 32), 256>>>(w1f, x, b1f, h, 1024, 256);

    // BN2 stats on h -> fold into W2 -> GEMM2 with mu/logvar scatter
    bn_stats_kernel<<<256, 256>>>(h, bn2_g, bn2_b, s2, t2, 256);
    fold_kernel<<<64, 256>>>(w2, b2, s2, t2, w2f, b2f, 256);
    gemm_tf32_kernel<64, 2, 1><<<dim3(16, 1, 32), 256>>>(w2f, h, b2f, out, 256, 64);
}

// round 10
// speedup vs baseline: 1.2745x; 1.2745x over previous
#include <cuda_runtime.h>
#include <cuda_fp16.h>
#include <cstdint>
#include <cstddef>

// ---------------------------------------------------------------------------
// Bottleneck: BN -> conv1x1(1024->256) -> relu -> BN -> conv1x1(256->64)
// B=32, C=1024, T=2048.  BN folded into GEMM weights.
// GEMM1: fp16 mma.sync m16n8k16 (2x tf32 rate, same 10-bit mantissa),
//        BN2 stats fused into epilogue (deterministic partials).
// GEMM2: tf32 mma.sync (proven).
// NOTE: no tcgen05 — harness PTX target is sm_103 (no 'a'), which rejects it.
// ---------------------------------------------------------------------------

#define EPSV 1e-5f
constexpr int Tdim = 2048;
constexpr int Bn   = 32;
constexpr int C1 = 1024, C2 = 256, C3 = 64;
constexpr int BN = 128;     // gemm2 t-tile
constexpr int BK = 16;      // gemm2 k-tile

// scratch (allocation-free rule: __device__ globals)
__device__ float    g_h[(size_t)Bn * C2 * Tdim];   // 64 MiB intermediate (fp32)
__device__ float    g_p1s[8 * C1], g_p1q[8 * C1];  // stats1 partials
__device__ float    g_s1[C1], g_t1[C1];
__device__ uint32_t g_w1h[C2 * (C1 / 2)];          // folded W1, packed half2 k-pairs
__device__ float    g_b1f[C2];
__device__ float    g_p2s[2 * 16 * 32 * 128];      // per-CTA BN2 partials
__device__ float    g_p2q[2 * 16 * 32 * 128];
__device__ float    g_s2[C2], g_t2[C2];
__device__ float    g_w2f[C3 * C2];
__device__ float    g_b2f[C3];

// ---------------------------------------------------------------------------
// helpers
// ---------------------------------------------------------------------------
__device__ __forceinline__ float to_tf32(float v) {
    uint32_t u;
    asm("cvt.rna.tf32.f32 %0, %1;" : "=r"(u) : "f"(v));
    return __uint_as_float(u);
}

__device__ __forceinline__ uint32_t pack_h2(float lo, float hi) {
    __half2 h = __floats2half2_rn(lo, hi);   // .x = lo (low 16 bits)
    return *reinterpret_cast<uint32_t*>(&h);
}

// fp16 mma: D(16x8) += A(16x16) * B(16x8), fp32 accumulate
__device__ __forceinline__ void mma16(float* c, const uint32_t* a, const uint32_t* b) {
    asm volatile(
        "mma.sync.aligned.m16n8k16.row.col.f32.f16.f16.f32 "
        "{%0,%1,%2,%3}, {%4,%5,%6,%7}, {%8,%9}, {%0,%1,%2,%3};"
        : "+f"(c[0]), "+f"(c[1]), "+f"(c[2]), "+f"(c[3])
        : "r"(a[0]), "r"(a[1]), "r"(a[2]), "r"(a[3]), "r"(b[0]), "r"(b[1]));
}

// tf32 mma for GEMM2
__device__ __forceinline__ void mma8(float* c, const uint32_t* a, const uint32_t* b) {
    asm volatile(
        "mma.sync.aligned.m16n8k8.row.col.f32.tf32.tf32.f32 "
        "{%0,%1,%2,%3}, {%4,%5,%6,%7}, {%8,%9}, {%0,%1,%2,%3};"
        : "+f"(c[0]), "+f"(c[1]), "+f"(c[2]), "+f"(c[3])
        : "r"(a[0]), "r"(a[1]), "r"(a[2]), "r"(a[3]), "r"(b[0]), "r"(b[1]));
}

// ---------------------------------------------------------------------------
// BN1 stats, split 8x over batch: block (c, q) sums batches q*4..q*4+3.
// ---------------------------------------------------------------------------
__global__ void bn1_part_kernel(const float* __restrict__ x,
                                float* __restrict__ ps, float* __restrict__ pq)
{
    const int c = blockIdx.x, q = blockIdx.y, tid = threadIdx.x;
    float s = 0.f, ss = 0.f;
    const size_t cstride = (size_t)C1 * Tdim;
    const float* base = x + (size_t)c * Tdim + (size_t)(q * 4) * cstride;
#pragma unroll
    for (int bb = 0; bb < 4; ++bb) {
        const float4* row = reinterpret_cast<const float4*>(base + (size_t)bb * cstride);
#pragma unroll
        for (int i = 0; i < 2; ++i) {
            float4 v = row[tid + i * 256];
            s  += (v.x + v.y) + (v.z + v.w);
            ss += (v.x * v.x + v.y * v.y) + (v.z * v.z + v.w * v.w);
        }
    }
#pragma unroll
    for (int o = 16; o > 0; o >>= 1) {
        s  += __shfl_xor_sync(0xffffffffu, s, o);
        ss += __shfl_xor_sync(0xffffffffu, ss, o);
    }
    __shared__ float rs[8], rss[8];
    if ((tid & 31) == 0) { rs[tid >> 5] = s; rss[tid >> 5] = ss; }
    __syncthreads();
    if (tid == 0) {
        float S = 0.f, SS = 0.f;
#pragma unroll
        for (int i = 0; i < 8; ++i) { S += rs[i]; SS += rss[i]; }
        ps[q * C1 + c] = S;
        pq[q * C1 + c] = SS;
    }
}

__global__ void finalize1_kernel(const float* __restrict__ ps,
                                 const float* __restrict__ pq,
                                 const float* __restrict__ gamma,
                                 const float* __restrict__ beta,
                                 float* __restrict__ s_out,
                                 float* __restrict__ t_out)
{
    int c = blockIdx.x * 256 + threadIdx.x;
    float S = 0.f, SS = 0.f;
#pragma unroll
    for (int q = 0; q < 8; ++q) { S += ps[q * C1 + c]; SS += pq[q * C1 + c]; }
    const float invN = 1.0f / (float)(Bn * Tdim);
    float mean = S * invN;
    float var  = SS * invN - mean * mean;
    float sc   = gamma[c] * rsqrtf(var + EPSV);
    s_out[c] = sc;
    t_out[c] = beta[c] - mean * sc;
}

// ---------------------------------------------------------------------------
// Fold BN1 into W1; emit packed half2 (k-pairs) + fp32 bias.
// ---------------------------------------------------------------------------
__global__ void fold1h_kernel(const float* __restrict__ w,
                              const float* __restrict__ bias_in,
                              const float* __restrict__ s,
                              const float* __restrict__ t,
                              uint32_t* __restrict__ wh,
                              float* __restrict__ bf)
{
    const int o = blockIdx.x, tid = threadIdx.x;
    float part = 0.f;
    for (int c2 = tid; c2 < C1 / 2; c2 += 256) {
        float w0 = w[(size_t)o * C1 + 2 * c2];
        float w1 = w[(size_t)o * C1 + 2 * c2 + 1];
        part += w0 * t[2 * c2] + w1 * t[2 * c2 + 1];
        wh[(size_t)o * (C1 / 2) + c2] = pack_h2(w0 * s[2 * c2], w1 * s[2 * c2 + 1]);
    }
#pragma unroll
    for (int off = 16; off > 0; off >>= 1)
        part += __shfl_xor_sync(0xffffffffu, part, off);
    __shared__ float red[8];
    if ((tid & 31) == 0) red[tid >> 5] = part;
    __syncthreads();
    if (tid == 0) {
        float tot = 0.f;
#pragma unroll
        for (int i = 0; i < 8; ++i) tot += red[i];
        bf[o] = bias_in[o] + tot;
    }
}

// Fold BN2 into W2 (fp32 out, tf32 GEMM2 rounds in-kernel).
__global__ void fold2_kernel(const float* __restrict__ w,
                             const float* __restrict__ bias_in,
                             const float* __restrict__ s,
                             const float* __restrict__ t,
                             float* __restrict__ wf,
                             float* __restrict__ bf, int K)
{
    const int o = blockIdx.x, tid = threadIdx.x;
    float part = 0.f;
    for (int c = tid; c < K; c += 256) {
        float wv = w[(size_t)o * K + c];
        wf[(size_t)o * K + c] = wv * s[c];
        part += wv * t[c];
    }
#pragma unroll
    for (int off = 16; off > 0; off >>= 1)
        part += __shfl_xor_sync(0xffffffffu, part, off);
    __shared__ float red[8];
    if ((tid & 31) == 0) red[tid >> 5] = part;
    __syncthreads();
    if (tid == 0) {
        float tot = 0.f;
#pragma unroll
        for (int i = 0; i < 8; ++i) tot += red[i];
        bf[o] = bias_in[o] + tot;
    }
}

// ---------------------------------------------------------------------------
// GEMM1 fp16: h[b,o,t] = relu( sum_k W[o,k]*X[b,k,t] + bias[o] )
// Block tile 128(o) x 128(t), BK=32 (16 half2 pairs), 8 warps (2x4),
// warp tile 64x32, mma.sync m16n8k16.  SMEM rows padded to 136 words
// (stride ≡ 8 mod 32 → conflict-free fragment LDS).
// Epilogue: bias+relu, fp32 h store, deterministic per-CTA BN2 partials.
// ---------------------------------------------------------------------------
constexpr int K2ROW = 136;    // padded SMEM row length in uints (half2 units)

__global__ __launch_bounds__(256, 1)
void gemm1_f16_kernel(const uint32_t* __restrict__ Ah, const float* __restrict__ X,
                      const float* __restrict__ bias, float* __restrict__ H,
                      float* __restrict__ part_s, float* __restrict__ part_q)
{
    __shared__ uint32_t As2[2][16 * K2ROW];
    __shared__ uint32_t Bs2[2][16 * K2ROW];
    __shared__ float    sstat[4][128][2];

    const int tid = threadIdx.x, wid = tid >> 5, lane = tid & 31;
    const int wrow = wid >> 2, wcol = wid & 3;
    const int gid  = lane >> 2, tig = lane & 3;
    const int b  = blockIdx.z;
    const int t0 = blockIdx.x * 128;
    const int m0 = blockIdx.y * 128;
    const float* Xb = X + (size_t)b * C1 * Tdim;

    float acc[4][4][4];
#pragma unroll
    for (int i = 0; i < 4; ++i)
#pragma unroll
        for (int j = 0; j < 4; ++j)
#pragma unroll
            for (int e = 0; e < 4; ++e) acc[i][j][e] = 0.f;

    // A global->smem mapping: 2 uint4 per thread (whole 128x16-pair tile)
    int row_a[2], q_a[2];
#pragma unroll
    for (int i = 0; i < 2; ++i) {
        int u = tid * 2 + i;
        row_a[i] = u >> 2;       // o row 0..127
        q_a[i]   = u & 3;        // which uint4 (4 k-pairs) in the row
    }
    // B mapping: thread handles k-pair row bj, t-chunk of 8
    const int bj  = tid >> 4;            // 0..15 (k2)
    const int btc = (tid & 15) * 8;      // t offset

    uint4  a_g[2];
    float4 f0, f1, g0, g1;

    auto loadA = [&](int k2b) {
#pragma unroll
        for (int i = 0; i < 2; ++i)
            a_g[i] = *reinterpret_cast<const uint4*>(
                &Ah[(size_t)(m0 + row_a[i]) * (C1 / 2) + k2b + q_a[i] * 4]);
    };
    auto loadB = [&](int k0) {
        const float* p0 = Xb + (size_t)(k0 + 2 * bj) * Tdim + t0 + btc;
        const float* p1 = p0 + Tdim;
        f0 = *reinterpret_cast<const float4*>(p0);
        f1 = *reinterpret_cast<const float4*>(p0 + 4);
        g0 = *reinterpret_cast<const float4*>(p1);
        g1 = *reinterpret_cast<const float4*>(p1 + 4);
    };
    auto stsA = [&](int buf) {
#pragma unroll
        for (int i = 0; i < 2; ++i) {
            const uint32_t* c = reinterpret_cast<const uint32_t*>(&a_g[i]);
#pragma unroll
            for (int j = 0; j < 4; ++j)
                As2[buf][(q_a[i] * 4 + j) * K2ROW + row_a[i]] = c[j];
        }
    };
    auto stsB = [&](int buf) {
        uint4 u0, u1;
        u0.x = pack_h2(f0.x, g0.x); u0.y = pack_h2(f0.y, g0.y);
        u0.z = pack_h2(f0.z, g0.z); u0.w = pack_h2(f0.w, g0.w);
        u1.x = pack_h2(f1.x, g1.x); u1.y = pack_h2(f1.y, g1.y);
        u1.z = pack_h2(f1.z, g1.z); u1.w = pack_h2(f1.w, g1.w);
        *reinterpret_cast<uint4*>(&Bs2[buf][bj * K2ROW + btc])     = u0;
        *reinterpret_cast<uint4*>(&Bs2[buf][bj * K2ROW + btc + 4]) = u1;
    };

    // prologue
    loadA(0); loadB(0); stsA(0); stsB(0);
    __syncthreads();

    for (int kt = 0; kt < 32; ++kt) {
        const int cur = kt & 1, nxt = cur ^ 1;
        const bool has_next = (kt + 1 < 32);
        if (has_next) { loadA((kt + 1) * 16); loadB((kt + 1) * 32); }

#pragma unroll
        for (int kc = 0; kc < 2; ++kc) {
            const int base0 = (kc * 8 + tig) * K2ROW;
            const int base1 = (kc * 8 + tig + 4) * K2ROW;
            uint32_t af[4][4], bfr[4][2];
#pragma unroll
            for (int mt = 0; mt < 4; ++mt) {
                const int r = wrow * 64 + mt * 16 + gid;
                af[mt][0] = As2[cur][base0 + r];
                af[mt][1] = As2[cur][base0 + r + 8];
                af[mt][2] = As2[cur][base1 + r];
                af[mt][3] = As2[cur][base1 + r + 8];
            }
#pragma unroll
            for (int nt = 0; nt < 4; ++nt) {
                const int cc = wcol * 32 + nt * 8 + gid;
                bfr[nt][0] = Bs2[cur][base0 + cc];
                bfr[nt][1] = Bs2[cur][base1 + cc];
            }
#pragma unroll
            for (int mt = 0; mt < 4; ++mt)
#pragma unroll
                for (int nt = 0; nt < 4; ++nt)
                    mma16(acc[mt][nt], af[mt], bfr[nt]);
        }

        if (has_next) { stsA(nxt); stsB(nxt); }
        __syncthreads();
    }

    // ---- epilogue: bias + relu + h store + deterministic BN2 partials ----
#pragma unroll
    for (int mt = 0; mt < 4; ++mt) {
        const int row_l = wrow * 64 + mt * 16 + gid;
        const int row   = m0 + row_l;
        const float bz0 = bias[row];
        const float bz1 = bias[row + 8];
        float rsum0 = 0.f, rss0 = 0.f, rsum1 = 0.f, rss1 = 0.f;
#pragma unroll
        for (int nt = 0; nt < 4; ++nt) {
            const int col = t0 + wcol * 32 + nt * 8 + tig * 2;
            float v00 = fmaxf(acc[mt][nt][0] + bz0, 0.f);
            float v01 = fmaxf(acc[mt][nt][1] + bz0, 0.f);
            float v10 = fmaxf(acc[mt][nt][2] + bz1, 0.f);
            float v11 = fmaxf(acc[mt][nt][3] + bz1, 0.f);
            float* Hp = H + ((size_t)b * C2 + row) * Tdim + col;
            *reinterpret_cast<float2*>(Hp) = make_float2(v00, v01);
            *reinterpret_cast<float2*>(Hp + (size_t)8 * Tdim) = make_float2(v10, v11);
            rsum0 += v00 + v01;  rss0 += v00 * v00 + v01 * v01;
            rsum1 += v10 + v11;  rss1 += v10 * v10 + v11 * v11;
        }
        // reduce across tig quad (lanes gid*4+tig)
#pragma unroll
        for (int o = 1; o < 4; o <<= 1) {
            rsum0 += __shfl_xor_sync(0xffffffffu, rsum0, o);
            rss0  += __shfl_xor_sync(0xffffffffu, rss0,  o);
            rsum1 += __shfl_xor_sync(0xffffffffu, rsum1, o);
            rss1  += __shfl_xor_sync(0xffffffffu, rss1,  o);
        }
        if (tig == 0) {
            sstat[wcol][row_l][0]     = rsum0;
            sstat[wcol][row_l][1]     = rss0;
            sstat[wcol][row_l + 8][0] = rsum1;
            sstat[wcol][row_l + 8][1] = rss1;
        }
    }
    __syncthreads();
    if (tid < 128) {
        float S  = sstat[0][tid][0] + sstat[1][tid][0]
                 + sstat[2][tid][0] + sstat[3][tid][0];
        float SS = sstat[0][tid][1] + sstat[1][tid][1]
                 + sstat[2][tid][1] + sstat[3][tid][1];
        const int cbase = (((blockIdx.y * 16 + blockIdx.x) * 32 + blockIdx.z) << 7);
        part_s[cbase + tid] = S;
        part_q[cbase + tid] = SS;
    }
}

// finalize BN2 scale/shift from per-CTA partials (deterministic)
__global__ void finalize2_kernel(const float* __restrict__ ps,
                                 const float* __restrict__ pq,
                                 const float* __restrict__ gamma,
                                 const float* __restrict__ beta,
                                 float* __restrict__ s_out,
                                 float* __restrict__ t_out)
{
    const int o = blockIdx.x;                 // 0..255
    const int mtile = o >> 7, row = o & 127;
    const int tid = threadIdx.x;
    float S = 0.f, SS = 0.f;
    for (int i = tid; i < 512; i += 256) {    // i = tt*32 + b
        int idx = ((mtile * 512 + i) << 7) + row;
        S += ps[idx]; SS += pq[idx];
    }
#pragma unroll
    for (int off = 16; off > 0; off >>= 1) {
        S  += __shfl_xor_sync(0xffffffffu, S, off);
        SS += __shfl_xor_sync(0xffffffffu, SS, off);
    }
    __shared__ float rs[8], rss[8];
    if ((tid & 31) == 0) { rs[tid >> 5] = S; rss[tid >> 5] = SS; }
    __syncthreads();
    if (tid == 0) {
        float T = 0.f, TT = 0.f;
#pragma unroll
        for (int i = 0; i < 8; ++i) { T += rs[i]; TT += rss[i]; }
        const float invN = 1.0f / (float)(Bn * Tdim);
        float mean = T * invN;
        float var  = TT * invN - mean * mean;
        float sc   = gamma[o] * rsqrtf(var + EPSV);
        s_out[o] = sc;
        t_out[o] = beta[o] - mean * sc;
    }
}

// ---------------------------------------------------------------------------
// GEMM2 (mma.sync tf32): out = W2f @ h + b2f, mu/logvar scatter.  (Proven.)
// ---------------------------------------------------------------------------
__global__ __launch_bounds__(256)
void gemm2_kernel(const float* __restrict__ A,
                  const float* __restrict__ X,
                  const float* __restrict__ bias,
                  float* __restrict__ Out, int K)
{
    constexpr int BM = 64, MT = 2, NT = 4;
    constexpr int AP = BM + 4, BP = BN + 4;
    constexpr int AF4 = (BM * BK) / (4 * 256);

    __shared__ float As[2][BK][AP];
    __shared__ float Bs[2][BK][BP];

    const int tid  = threadIdx.x;
    const int wid  = tid >> 5, lane = tid & 31;
    const int wrow = wid >> 2, wcol = wid & 3;
    const int gid  = lane >> 2, tig = lane & 3;

    const int b  = blockIdx.z;
    const int t0 = blockIdx.x * BN;

    const float* Xb = X + (size_t)b * K * Tdim;

    float acc[MT][NT][4];
#pragma unroll
    for (int i = 0; i < MT; ++i)
#pragma unroll
        for (int j = 0; j < NT; ++j)
#pragma unroll
            for (int e = 0; e < 4; ++e) acc[i][j][e] = 0.f;

    int ar[AF4], aj[AF4];
#pragma unroll
    for (int i = 0; i < AF4; ++i) {
        int id = tid + i * 256;
        ar[i] = id >> 2;
        aj[i] = (id & 3) * 4;
    }
    const int bkb = tid >> 5;
    const int bnn = lane * 4;

    {
#pragma unroll
        for (int i = 0; i < AF4; ++i) {
            float4 v = *reinterpret_cast<const float4*>(A + (size_t)ar[i] * K + aj[i]);
            As[0][aj[i] + 0][ar[i]] = to_tf32(v.x);
            As[0][aj[i] + 1][ar[i]] = to_tf32(v.y);
            As[0][aj[i] + 2][ar[i]] = to_tf32(v.z);
            As[0][aj[i] + 3][ar[i]] = to_tf32(v.w);
        }
#pragma unroll
        for (int i = 0; i < 2; ++i) {
            int k = bkb + i * 8;
            float4 v = *reinterpret_cast<const float4*>(Xb + (size_t)k * Tdim + t0 + bnn);
            float4 c4 = make_float4(to_tf32(v.x), to_tf32(v.y), to_tf32(v.z), to_tf32(v.w));
            *reinterpret_cast<float4*>(&Bs[0][k][bnn]) = c4;
        }
    }
    __syncthreads();

    const int KT = K / BK;
    float4 a_reg[AF4], b_reg[2];

    for (int kt = 0; kt < KT; ++kt) {
        const int cur = kt & 1;
        const bool has_next = (kt + 1 < KT);
        if (has_next) {
            const int k0 = (kt + 1) * BK;
#pragma unroll
            for (int i = 0; i < AF4; ++i)
                a_reg[i] = *reinterpret_cast<const float4*>(
                    A + (size_t)ar[i] * K + k0 + aj[i]);
#pragma unroll
            for (int i = 0; i < 2; ++i) {
                int k = bkb + i * 8;
                b_reg[i] = *reinterpret_cast<const float4*>(
                    Xb + (size_t)(k0 + k) * Tdim + t0 + bnn);
            }
        }

#pragma unroll
        for (int kc = 0; kc < 2; ++kc) {
            const int kk = kc * 8 + tig;
            uint32_t af[MT][4], bfr[NT][2];
#pragma unroll
            for (int mt = 0; mt < MT; ++mt) {
                const int r = wrow * (BM / 2) + mt * 16 + gid;
                af[mt][0] = __float_as_uint(As[cur][kk    ][r]);
                af[mt][1] = __float_as_uint(As[cur][kk    ][r + 8]);
                af[mt][2] = __float_as_uint(As[cur][kk + 4][r]);
                af[mt][3] = __float_as_uint(As[cur][kk + 4][r + 8]);
            }
#pragma unroll
            for (int nt = 0; nt < NT; ++nt) {
                const int cc = wcol * 32 + nt * 8 + gid;
                bfr[nt][0] = __float_as_uint(Bs[cur][kk    ][cc]);
                bfr[nt][1] = __float_as_uint(Bs[cur][kk + 4][cc]);
            }
#pragma unroll
            for (int mt = 0; mt < MT; ++mt)
#pragma unroll
                for (int nt = 0; nt < NT; ++nt)
                    mma8(acc[mt][nt], af[mt], bfr[nt]);
        }

        if (has_next) {
            const int nb = cur ^ 1;
#pragma unroll
            for (int i = 0; i < AF4; ++i) {
                As[nb][aj[i] + 0][ar[i]] = to_tf32(a_reg[i].x);
                As[nb][aj[i] + 1][ar[i]] = to_tf32(a_reg[i].y);
                As[nb][aj[i] + 2][ar[i]] = to_tf32(a_reg[i].z);
                As[nb][aj[i] + 3][ar[i]] = to_tf32(a_reg[i].w);
            }
#pragma unroll
            for (int i = 0; i < 2; ++i) {
                int k = bkb + i * 8;
                float4 c4 = make_float4(to_tf32(b_reg[i].x), to_tf32(b_reg[i].y),
                                        to_tf32(b_reg[i].z), to_tf32(b_reg[i].w));
                *reinterpret_cast<float4*>(&Bs[nb][k][bnn]) = c4;
            }
        }
        __syncthreads();
    }

#pragma unroll
    for (int mt = 0; mt < MT; ++mt) {
        const int row = wrow * (BM / 2) + mt * 16 + gid;
        const float bz0 = bias[row];
        const float bz1 = bias[row + 8];
#pragma unroll
        for (int nt = 0; nt < NT; ++nt) {
            const int col = t0 + wcol * 32 + nt * 8 + tig * 2;
            const int row1 = row + 8;
            size_t i0 = (row < 32)
                ? ((size_t)b * 65536 + (size_t)row * Tdim)
                : (2097152 + (size_t)b * 65536 + (size_t)(row - 32) * Tdim);
            size_t i1 = (row1 < 32)
                ? ((size_t)b * 65536 + (size_t)row1 * Tdim)
                : (2097152 + (size_t)b * 65536 + (size_t)(row1 - 32) * Tdim);
            float2 v0 = make_float2(acc[mt][nt][0] + bz0, acc[mt][nt][1] + bz0);
            float2 v1 = make_float2(acc[mt][nt][2] + bz1, acc[mt][nt][3] + bz1);
            *reinterpret_cast<float2*>(Out + i0 + col) = v0;
            *reinterpret_cast<float2*>(Out + i1 + col) = v1;
        }
    }
}

// ---------------------------------------------------------------------------
extern "C" void kernel_launch(void* const* d_in, const int* in_sizes, int n_in,
                              void* d_out, int out_size)
{
    const float* x     = (const float*)d_in[0];
    const float* bn1_g = (const float*)d_in[1];
    const float* bn1_b = (const float*)d_in[2];
    const float* w1    = (const float*)d_in[3];
    const float* b1    = (const float*)d_in[4];
    const float* bn2_g = (const float*)d_in[5];
    const float* bn2_b = (const float*)d_in[6];
    const float* w2    = (const float*)d_in[7];
    const float* b2    = (const float*)d_in[8];
    float* out = (float*)d_out;

    float *h, *p1s, *p1q, *s1, *t1, *b1f, *p2s, *p2q, *s2, *t2, *w2f, *b2f;
    uint32_t* w1h;
    cudaGetSymbolAddress((void**)&h,   g_h);
    cudaGetSymbolAddress((void**)&p1s, g_p1s);
    cudaGetSymbolAddress((void**)&p1q, g_p1q);
    cudaGetSymbolAddress((void**)&s1,  g_s1);
    cudaGetSymbolAddress((void**)&t1,  g_t1);
    cudaGetSymbolAddress((void**)&w1h, g_w1h);
    cudaGetSymbolAddress((void**)&b1f, g_b1f);
    cudaGetSymbolAddress((void**)&p2s, g_p2s);
    cudaGetSymbolAddress((void**)&p2q, g_p2q);
    cudaGetSymbolAddress((void**)&s2,  g_s2);
    cudaGetSymbolAddress((void**)&t2,  g_t2);
    cudaGetSymbolAddress((void**)&w2f, g_w2f);
    cudaGetSymbolAddress((void**)&b2f, g_b2f);

    // BN1 stats (8-way split) -> scale/shift -> fold into W1 (fp16 pairs)
    bn1_part_kernel<<<dim3(C1, 8), 256>>>(x, p1s, p1q);
    finalize1_kernel<<<4, 256>>>(p1s, p1q, bn1_g, bn1_b, s1, t1);
    fold1h_kernel<<<C2, 256>>>(w1, b1, s1, t1, w1h, b1f);

    // GEMM1 fp16 with fused (deterministic) BN2 partial stats
    gemm1_f16_kernel<<<dim3(16, 2, 32), 256>>>(w1h, x, b1f, h, p2s, p2q);

    // finalize BN2 -> fold into W2 -> GEMM2 with mu/logvar scatter
    finalize2_kernel<<<C2, 256>>>(p2s, p2q, bn2_g, bn2_b, s2, t2);
    fold2_kernel<<<C3, 256>>>(w2, b2, s2, t2, w2f, b2f, C2);
    gemm2_kernel<<<dim3(Tdim / BN, 1, Bn), 256>>>(w2f, h, b2f, out, C2);
}

// round 12
// speedup vs baseline: 1.9369x; 1.5197x over previous
#include <cuda_runtime.h>
#include <cuda_fp16.h>
#include <cstdint>
#include <cstddef>

// ---------------------------------------------------------------------------
// Bottleneck: BN -> conv1x1(1024->256) -> relu -> BN -> conv1x1(256->64)
// B=32, C=1024, T=2048.  BN folded into GEMM weights.
// x materialized once to fp16 inside bn1-stats; both GEMMs are fp16
// mma.sync m16n8k16 with cp.async global->SMEM tiles and ldmatrix fragment
// loads.  h kept in fp16.  BN2 stats fused into GEMM1 epilogue.
// ---------------------------------------------------------------------------

#define EPSV 1e-5f
constexpr int Tdim = 2048;
constexpr int Bn   = 32;
constexpr int C1 = 1024, C2 = 256, C3 = 64;

// scratch (allocation-free rule: __device__ globals)
__device__ __half   g_xh[(size_t)Bn * C1 * Tdim];  // 128 MiB x in fp16
__device__ __half   g_h[(size_t)Bn * C2 * Tdim];   // 32 MiB intermediate fp16
__device__ float    g_p1s[8 * C1], g_p1q[8 * C1];  // stats1 partials
__device__ float    g_s1[C1], g_t1[C1];
__device__ uint32_t g_w1h[C2 * (C1 / 2)];          // folded W1, half2 k-pairs
__device__ float    g_b1f[C2];
__device__ float    g_p2s[2 * 16 * 32 * 128];      // per-CTA BN2 partials
__device__ float    g_p2q[2 * 16 * 32 * 128];
__device__ float    g_s2[C2], g_t2[C2];
__device__ uint32_t g_w2h[C3 * (C2 / 2)];          // folded W2, half2 k-pairs
__device__ float    g_b2f[C3];

// ---------------------------------------------------------------------------
// helpers
// ---------------------------------------------------------------------------
__device__ __forceinline__ uint32_t pack_h2(float lo, float hi) {
    __half2 h = __floats2half2_rn(lo, hi);
    return *reinterpret_cast<uint32_t*>(&h);
}

__device__ __forceinline__ uint32_t smem_u32(const void* p) {
    uint32_t a;
    asm("{ .reg .u64 t; cvta.to.shared.u64 t, %1; cvt.u32.u64 %0, t; }"
        : "=r"(a) : "l"(p));
    return a;
}

__device__ __forceinline__ void mma16(float* c, const uint32_t* a, const uint32_t* b) {
    asm volatile(
        "mma.sync.aligned.m16n8k16.row.col.f32.f16.f16.f32 "
        "{%0,%1,%2,%3}, {%4,%5,%6,%7}, {%8,%9}, {%0,%1,%2,%3};"
        : "+f"(c[0]), "+f"(c[1]), "+f"(c[2]), "+f"(c[3])
        : "r"(a[0]), "r"(a[1]), "r"(a[2]), "r"(a[3]), "r"(b[0]), "r"(b[1]));
}

#define CP16(dst, src) \
    asm volatile("cp.async.cg.shared.global [%0], [%1], 16;" \
                 :: "r"(dst), "l"(src) : "memory")
#define CP_COMMIT()  asm volatile("cp.async.commit_group;" ::: "memory")
#define CP_WAIT0()   asm volatile("cp.async.wait_group 0;" ::: "memory")
#define CP_WAIT1()   asm volatile("cp.async.wait_group 1;" ::: "memory")

#define LDSM4(r0, r1, r2, r3, a) \
    asm volatile("ldmatrix.sync.aligned.m8n8.x4.shared.b16 {%0,%1,%2,%3}, [%4];" \
                 : "=r"(r0), "=r"(r1), "=r"(r2), "=r"(r3) : "r"(a))
#define LDSM4T(r0, r1, r2, r3, a) \
    asm volatile("ldmatrix.sync.aligned.m8n8.x4.trans.shared.b16 {%0,%1,%2,%3}, [%4];" \
                 : "=r"(r0), "=r"(r1), "=r"(r2), "=r"(r3) : "r"(a))

// SMEM geometry shared by both GEMMs
constexpr int AS_STRIDE = 80;              // A row: 32 halves + 8 pad (bytes)
constexpr int BS_STRIDE = 272;             // B row: 128 halves + 8 pad (bytes)
constexpr int BS_BUF    = 32 * BS_STRIDE;  // 8704 B per buffer

// ---------------------------------------------------------------------------
// BN1 stats (8-way batch split) + fp16 materialization of x.
// block (c, q): batches q*4..q*4+3, full T.  Also writes xh[b][c][t].
// ---------------------------------------------------------------------------
__global__ void bn1_part_kernel(const float* __restrict__ x,
                                float* __restrict__ ps, float* __restrict__ pq,
                                __half* __restrict__ xh)
{
    const int c = blockIdx.x, q = blockIdx.y, tid = threadIdx.x;
    float s = 0.f, ss = 0.f;
    const size_t cstride = (size_t)C1 * Tdim;
#pragma unroll
    for (int bb = 0; bb < 4; ++bb) {
        const size_t rowoff = (size_t)(q * 4 + bb) * cstride + (size_t)c * Tdim;
        const float4* row = reinterpret_cast<const float4*>(x + rowoff);
        float4 v0 = row[tid * 2];
        float4 v1 = row[tid * 2 + 1];
        s  += (v0.x + v0.y) + (v0.z + v0.w) + (v1.x + v1.y) + (v1.z + v1.w);
        ss += (v0.x * v0.x + v0.y * v0.y) + (v0.z * v0.z + v0.w * v0.w)
            + (v1.x * v1.x + v1.y * v1.y) + (v1.z * v1.z + v1.w * v1.w);
        uint4 o4;
        o4.x = pack_h2(v0.x, v0.y); o4.y = pack_h2(v0.z, v0.w);
        o4.z = pack_h2(v1.x, v1.y); o4.w = pack_h2(v1.z, v1.w);
        *reinterpret_cast<uint4*>(xh + rowoff + tid * 8) = o4;
    }
#pragma unroll
    for (int o = 16; o > 0; o >>= 1) {
        s  += __shfl_xor_sync(0xffffffffu, s, o);
        ss += __shfl_xor_sync(0xffffffffu, ss, o);
    }
    __shared__ float rs[8], rss[8];
    if ((tid & 31) == 0) { rs[tid >> 5] = s; rss[tid >> 5] = ss; }
    __syncthreads();
    if (tid == 0) {
        float S = 0.f, SS = 0.f;
#pragma unroll
        for (int i = 0; i < 8; ++i) { S += rs[i]; SS += rss[i]; }
        ps[q * C1 + c] = S;
        pq[q * C1 + c] = SS;
    }
}

__global__ void finalize1_kernel(const float* __restrict__ ps,
                                 const float* __restrict__ pq,
                                 const float* __restrict__ gamma,
                                 const float* __restrict__ beta,
                                 float* __restrict__ s_out,
                                 float* __restrict__ t_out)
{
    int c = blockIdx.x * 256 + threadIdx.x;
    float S = 0.f, SS = 0.f;
#pragma unroll
    for (int q = 0; q < 8; ++q) { S += ps[q * C1 + c]; SS += pq[q * C1 + c]; }
    const float invN = 1.0f / (float)(Bn * Tdim);
    float mean = S * invN;
    float var  = SS * invN - mean * mean;
    float sc   = gamma[c] * rsqrtf(var + EPSV);
    s_out[c] = sc;
    t_out[c] = beta[c] - mean * sc;
}

// ---------------------------------------------------------------------------
// Fold BN1 into W1; emit packed half2 (k-pairs) + fp32 bias.
// ---------------------------------------------------------------------------
__global__ void fold1h_kernel(const float* __restrict__ w,
                              const float* __restrict__ bias_in,
                              const float* __restrict__ s,
                              const float* __restrict__ t,
                              uint32_t* __restrict__ wh,
                              float* __restrict__ bf)
{
    const int o = blockIdx.x, tid = threadIdx.x;
    float part = 0.f;
    for (int c2 = tid; c2 < C1 / 2; c2 += 256) {
        float w0 = w[(size_t)o * C1 + 2 * c2];
        float w1 = w[(size_t)o * C1 + 2 * c2 + 1];
        part += w0 * t[2 * c2] + w1 * t[2 * c2 + 1];
        wh[(size_t)o * (C1 / 2) + c2] = pack_h2(w0 * s[2 * c2], w1 * s[2 * c2 + 1]);
    }
#pragma unroll
    for (int off = 16; off > 0; off >>= 1)
        part += __shfl_xor_sync(0xffffffffu, part, off);
    __shared__ float red[8];
    if ((tid & 31) == 0) red[tid >> 5] = part;
    __syncthreads();
    if (tid == 0) {
        float tot = 0.f;
#pragma unroll
        for (int i = 0; i < 8; ++i) tot += red[i];
        bf[o] = bias_in[o] + tot;
    }
}

// Fold BN2 into W2 (half2 pairs).  64 blocks x 128 threads.
__global__ void fold2h_kernel(const float* __restrict__ w,
                              const float* __restrict__ bias_in,
                              const float* __restrict__ s,
                              const float* __restrict__ t,
                              uint32_t* __restrict__ wh,
                              float* __restrict__ bf)
{
    const int o = blockIdx.x, tid = threadIdx.x;   // tid = c2, 0..127
    float w0 = w[(size_t)o * C2 + 2 * tid];
    float w1 = w[(size_t)o * C2 + 2 * tid + 1];
    float part = w0 * t[2 * tid] + w1 * t[2 * tid + 1];
    wh[(size_t)o * (C2 / 2) + tid] = pack_h2(w0 * s[2 * tid], w1 * s[2 * tid + 1]);
#pragma unroll
    for (int off = 16; off > 0; off >>= 1)
        part += __shfl_xor_sync(0xffffffffu, part, off);
    __shared__ float red[4];
    if ((tid & 31) == 0) red[tid >> 5] = part;
    __syncthreads();
    if (tid == 0)
        bf[o] = bias_in[o] + red[0] + red[1] + red[2] + red[3];
}

// ---------------------------------------------------------------------------
// GEMM1 fp16: h[b,o,t] = relu( sum_k W[o,k]*X[b,k,t] + bias[o] )   (fp16 out)
// Block 128(o) x 128(t), BK=32, 8 warps (2x4), warp tile 64x32.
// cp.async tiles (A half [o][k] rows, B half [k][t] rows), ldmatrix frags.
// Epilogue: bias+relu, fp16 h store, deterministic per-CTA BN2 partials.
// ---------------------------------------------------------------------------
constexpr int AS1_BUF = 128 * AS_STRIDE;   // 10240 B per buffer

__global__ __launch_bounds__(256, 2)
void gemm1_f16_kernel(const uint32_t* __restrict__ Ah,
                      const __half* __restrict__ Xh,
                      const float* __restrict__ bias,
                      __half* __restrict__ H,
                      float* __restrict__ part_s, float* __restrict__ part_q)
{
    __shared__ __align__(16) char Asm[2 * AS1_BUF];
    __shared__ __align__(16) char Bsm[2 * BS_BUF];
    __shared__ float sstat[4][128][2];

    const int tid = threadIdx.x, wid = tid >> 5, lane = tid & 31;
    const int wrow = wid >> 2, wcol = wid & 3;
    const int gid  = lane >> 2, tig = lane & 3;
    const int b  = blockIdx.z;
    const int t0 = blockIdx.x * 128;
    const int m0 = blockIdx.y * 128;

    const uint32_t as0 = smem_u32(Asm), bs0 = smem_u32(Bsm);

    float acc[4][4][4];
#pragma unroll
    for (int i = 0; i < 4; ++i)
#pragma unroll
        for (int j = 0; j < 4; ++j)
#pragma unroll
            for (int e = 0; e < 4; ++e) acc[i][j][e] = 0.f;

    auto issue = [&](int kt, int buf) {
        const uint32_t ab = as0 + buf * AS1_BUF;
        const uint32_t bb = bs0 + buf * BS_BUF;
#pragma unroll
        for (int i = 0; i < 2; ++i) {
            const int u = tid * 2 + i;
            const int o = u >> 2, j = u & 3;           // A: 128 rows x 4 chunks
            CP16(ab + o * AS_STRIDE + j * 16,
                 (const char*)Ah + (size_t)(m0 + o) * 2048 + kt * 64 + j * 16);
            const int k = u >> 4, c = u & 15;          // B: 32 rows x 16 chunks
            CP16(bb + k * BS_STRIDE + c * 16,
                 (const char*)Xh +
                 (((size_t)b * C1 + kt * 32 + k) * Tdim + t0 + c * 8) * 2);
        }
        CP_COMMIT();
    };

    issue(0, 0);
    for (int kt = 0; kt < 32; ++kt) {
        const int cur = kt & 1;
        if (kt + 1 < 32) { issue(kt + 1, cur ^ 1); CP_WAIT1(); }
        else             { CP_WAIT0(); }
        __syncthreads();

        const uint32_t ab = as0 + cur * AS1_BUF;
        const uint32_t bb = bs0 + cur * BS_BUF;
        const int g = lane >> 3;
        const int krow = ((g & 1) << 3) + (lane & 7);
        const int ncol = (g >> 1) << 3;
#pragma unroll
        for (int kc = 0; kc < 2; ++kc) {
            uint32_t af[4][4], bf[4][2];
#pragma unroll
            for (int mt = 0; mt < 4; ++mt) {
                uint32_t addr = ab + (wrow * 64 + mt * 16 + (lane & 15)) * AS_STRIDE
                              + kc * 32 + ((lane >> 4) << 4);
                LDSM4(af[mt][0], af[mt][1], af[mt][2], af[mt][3], addr);
            }
#pragma unroll
            for (int pr = 0; pr < 2; ++pr) {
                uint32_t addr = bb + (kc * 16 + krow) * BS_STRIDE
                              + (wcol * 32 + pr * 16 + ncol) * 2;
                LDSM4T(bf[pr * 2][0], bf[pr * 2][1],
                       bf[pr * 2 + 1][0], bf[pr * 2 + 1][1], addr);
            }
#pragma unroll
            for (int mt = 0; mt < 4; ++mt)
#pragma unroll
                for (int nt = 0; nt < 4; ++nt)
                    mma16(acc[mt][nt], af[mt], bf[nt]);
        }
        __syncthreads();
    }

    // ---- epilogue: bias + relu + fp16 h store + deterministic BN2 partials
#pragma unroll
    for (int mt = 0; mt < 4; ++mt) {
        const int row_l = wrow * 64 + mt * 16 + gid;
        const int row   = m0 + row_l;
        const float bz0 = bias[row];
        const float bz1 = bias[row + 8];
        float rsum0 = 0.f, rss0 = 0.f, rsum1 = 0.f, rss1 = 0.f;
#pragma unroll
        for (int nt = 0; nt < 4; ++nt) {
            const int col = t0 + wcol * 32 + nt * 8 + tig * 2;
            float v00 = fmaxf(acc[mt][nt][0] + bz0, 0.f);
            float v01 = fmaxf(acc[mt][nt][1] + bz0, 0.f);
            float v10 = fmaxf(acc[mt][nt][2] + bz1, 0.f);
            float v11 = fmaxf(acc[mt][nt][3] + bz1, 0.f);
            *reinterpret_cast<__half2*>(H + ((size_t)b * C2 + row) * Tdim + col)
                = __floats2half2_rn(v00, v01);
            *reinterpret_cast<__half2*>(H + ((size_t)b * C2 + row + 8) * Tdim + col)
                = __floats2half2_rn(v10, v11);
            rsum0 += v00 + v01;  rss0 += v00 * v00 + v01 * v01;
            rsum1 += v10 + v11;  rss1 += v10 * v10 + v11 * v11;
        }
#pragma unroll
        for (int o = 1; o < 4; o <<= 1) {
            rsum0 += __shfl_xor_sync(0xffffffffu, rsum0, o);
            rss0  += __shfl_xor_sync(0xffffffffu, rss0,  o);
            rsum1 += __shfl_xor_sync(0xffffffffu, rsum1, o);
            rss1  += __shfl_xor_sync(0xffffffffu, rss1,  o);
        }
        if (tig == 0) {
            sstat[wcol][row_l][0]     = rsum0;
            sstat[wcol][row_l][1]     = rss0;
            sstat[wcol][row_l + 8][0] = rsum1;
            sstat[wcol][row_l + 8][1] = rss1;
        }
    }
    __syncthreads();
    if (tid < 128) {
        float S  = sstat[0][tid][0] + sstat[1][tid][0]
                 + sstat[2][tid][0] + sstat[3][tid][0];
        float SS = sstat[0][tid][1] + sstat[1][tid][1]
                 + sstat[2][tid][1] + sstat[3][tid][1];
        const int cbase = (((blockIdx.y * 16 + blockIdx.x) * 32 + blockIdx.z) << 7);
        part_s[cbase + tid] = S;
        part_q[cbase + tid] = SS;
    }
}

// finalize BN2 scale/shift from per-CTA partials (deterministic)
__global__ void finalize2_kernel(const float* __restrict__ ps,
                                 const float* __restrict__ pq,
                                 const float* __restrict__ gamma,
                                 const float* __restrict__ beta,
                                 float* __restrict__ s_out,
                                 float* __restrict__ t_out)
{
    const int o = blockIdx.x;
    const int mtile = o >> 7, row = o & 127;
    const int tid = threadIdx.x;
    float S = 0.f, SS = 0.f;
    for (int i = tid; i < 512; i += 256) {
        int idx = ((mtile * 512 + i) << 7) + row;
        S += ps[idx]; SS += pq[idx];
    }
#pragma unroll
    for (int off = 16; off > 0; off >>= 1) {
        S  += __shfl_xor_sync(0xffffffffu, S, off);
        SS += __shfl_xor_sync(0xffffffffu, SS, off);
    }
    __shared__ float rs[8], rss[8];
    if ((tid & 31) == 0) { rs[tid >> 5] = S; rss[tid >> 5] = SS; }
    __syncthreads();
    if (tid == 0) {
        float T = 0.f, TT = 0.f;
#pragma unroll
        for (int i = 0; i < 8; ++i) { T += rs[i]; TT += rss[i]; }
        const float invN = 1.0f / (float)(Bn * Tdim);
        float mean = T * invN;
        float var  = TT * invN - mean * mean;
        float sc   = gamma[o] * rsqrtf(var + EPSV);
        s_out[o] = sc;
        t_out[o] = beta[o] - mean * sc;
    }
}

// ---------------------------------------------------------------------------
// GEMM2 fp16: out = W2f @ h + b2f, mu/logvar scatter (fp32 out).
// Block 64(o) x 128(t), BK=32, 8 warps (2x4), warp tile 32x32, K=256.
// ---------------------------------------------------------------------------
constexpr int AS2_BUF = 64 * AS_STRIDE;    // 5120 B per buffer

__global__ __launch_bounds__(256, 2)
void gemm2_f16_kernel(const uint32_t* __restrict__ Ah,
                      const __half* __restrict__ Hh,
                      const float* __restrict__ bias,
                      float* __restrict__ Out)
{
    __shared__ __align__(16) char Asm[2 * AS2_BUF];
    __shared__ __align__(16) char Bsm[2 * BS_BUF];

    const int tid = threadIdx.x, wid = tid >> 5, lane = tid & 31;
    const int wrow = wid >> 2, wcol = wid & 3;
    const int gid  = lane >> 2, tig = lane & 3;
    const int b  = blockIdx.z;
    const int t0 = blockIdx.x * 128;

    const uint32_t as0 = smem_u32(Asm), bs0 = smem_u32(Bsm);

    float acc[2][4][4];
#pragma unroll
    for (int i = 0; i < 2; ++i)
#pragma unroll
        for (int j = 0; j < 4; ++j)
#pragma unroll
            for (int e = 0; e < 4; ++e) acc[i][j][e] = 0.f;

    auto issue = [&](int kt, int buf) {
        const uint32_t ab = as0 + buf * AS2_BUF;
        const uint32_t bb = bs0 + buf * BS_BUF;
        {   // A: 64 rows x 4 chunks = 256, 1 per thread
            const int o = tid >> 2, j = tid & 3;
            CP16(ab + o * AS_STRIDE + j * 16,
                 (const char*)Ah + (size_t)o * 512 + kt * 64 + j * 16);
        }
#pragma unroll
        for (int i = 0; i < 2; ++i) {                  // B: 512, 2 per thread
            const int u = tid * 2 + i;
            const int k = u >> 4, c = u & 15;
            CP16(bb + k * BS_STRIDE + c * 16,
                 (const char*)Hh +
                 (((size_t)b * C2 + kt * 32 + k) * Tdim + t0 + c * 8) * 2);
        }
        CP_COMMIT();
    };

    issue(0, 0);
    for (int kt = 0; kt < 8; ++kt) {
        const int cur = kt & 1;
        if (kt + 1 < 8) { issue(kt + 1, cur ^ 1); CP_WAIT1(); }
        else            { CP_WAIT0(); }
        __syncthreads();

        const uint32_t ab = as0 + cur * AS2_BUF;
        const uint32_t bb = bs0 + cur * BS_BUF;
        const int g = lane >> 3;
        const int krow = ((g & 1) << 3) + (lane & 7);
        const int ncol = (g >> 1) << 3;
#pragma unroll
        for (int kc = 0; kc < 2; ++kc) {
            uint32_t af[2][4], bf[4][2];
#pragma unroll
            for (int mt = 0; mt < 2; ++mt) {
                uint32_t addr = ab + (wrow * 32 + mt * 16 + (lane & 15)) * AS_STRIDE
                              + kc * 32 + ((lane >> 4) << 4);
                LDSM4(af[mt][0], af[mt][1], af[mt][2], af[mt][3], addr);
            }
#pragma unroll
            for (int pr = 0; pr < 2; ++pr) {
                uint32_t addr = bb + (kc * 16 + krow) * BS_STRIDE
                              + (wcol * 32 + pr * 16 + ncol) * 2;
                LDSM4T(bf[pr * 2][0], bf[pr * 2][1],
                       bf[pr * 2 + 1][0], bf[pr * 2 + 1][1], addr);
            }
#pragma unroll
            for (int mt = 0; mt < 2; ++mt)
#pragma unroll
                for (int nt = 0; nt < 4; ++nt)
                    mma16(acc[mt][nt], af[mt], bf[nt]);
        }
        __syncthreads();
    }

    // epilogue: bias + mu/logvar scatter (fp32 out)
#pragma unroll
    for (int mt = 0; mt < 2; ++mt) {
        const int row = wrow * 32 + mt * 16 + gid;
        const float bz0 = bias[row];
        const float bz1 = bias[row + 8];
#pragma unroll
        for (int nt = 0; nt < 4; ++nt) {
            const int col = t0 + wcol * 32 + nt * 8 + tig * 2;
            const int row1 = row + 8;
            size_t i0 = (row < 32)
                ? ((size_t)b * 65536 + (size_t)row * Tdim)
                : (2097152 + (size_t)b * 65536 + (size_t)(row - 32) * Tdim);
            size_t i1 = (row1 < 32)
                ? ((size_t)b * 65536 + (size_t)row1 * Tdim)
                : (2097152 + (size_t)b * 65536 + (size_t)(row1 - 32) * Tdim);
            float2 v0 = make_float2(acc[mt][nt][0] + bz0, acc[mt][nt][1] + bz0);
            float2 v1 = make_float2(acc[mt][nt][2] + bz1, acc[mt][nt][3] + bz1);
            *reinterpret_cast<float2*>(Out + i0 + col) = v0;
            *reinterpret_cast<float2*>(Out + i1 + col) = v1;
        }
    }
}

// ---------------------------------------------------------------------------
extern "C" void kernel_launch(void* const* d_in, const int* in_sizes, int n_in,
                              void* d_out, int out_size)
{
    const float* x     = (const float*)d_in[0];
    const float* bn1_g = (const float*)d_in[1];
    const float* bn1_b = (const float*)d_in[2];
    const float* w1    = (const float*)d_in[3];
    const float* b1    = (const float*)d_in[4];
    const float* bn2_g = (const float*)d_in[5];
    const float* bn2_b = (const float*)d_in[6];
    const float* w2    = (const float*)d_in[7];
    const float* b2    = (const float*)d_in[8];
    float* out = (float*)d_out;

    __half *xh, *h;
    float *p1s, *p1q, *s1, *t1, *b1f, *p2s, *p2q, *s2, *t2, *b2f;
    uint32_t *w1h, *w2h;
    cudaGetSymbolAddress((void**)&xh,  g_xh);
    cudaGetSymbolAddress((void**)&h,   g_h);
    cudaGetSymbolAddress((void**)&p1s, g_p1s);
    cudaGetSymbolAddress((void**)&p1q, g_p1q);
    cudaGetSymbolAddress((void**)&s1,  g_s1);
    cudaGetSymbolAddress((void**)&t1,  g_t1);
    cudaGetSymbolAddress((void**)&w1h, g_w1h);
    cudaGetSymbolAddress((void**)&b1f, g_b1f);
    cudaGetSymbolAddress((void**)&p2s, g_p2s);
    cudaGetSymbolAddress((void**)&p2q, g_p2q);
    cudaGetSymbolAddress((void**)&s2,  g_s2);
    cudaGetSymbolAddress((void**)&t2,  g_t2);
    cudaGetSymbolAddress((void**)&w2h, g_w2h);
    cudaGetSymbolAddress((void**)&b2f, g_b2f);

    // BN1 stats + x->fp16 materialization -> scale/shift -> fold W1 (fp16)
    bn1_part_kernel<<<dim3(C1, 8), 256>>>(x, p1s, p1q, xh);
    finalize1_kernel<<<4, 256>>>(p1s, p1q, bn1_g, bn1_b, s1, t1);
    fold1h_kernel<<<C2, 256>>>(w1, b1, s1, t1, w1h, b1f);

    // GEMM1 fp16 (cp.async + ldmatrix) with fused BN2 partial stats
    gemm1_f16_kernel<<<dim3(16, 2, 32), 256>>>(w1h, xh, b1f, h, p2s, p2q);

    // finalize BN2 -> fold W2 (fp16) -> GEMM2 fp16 with mu/logvar scatter
    finalize2_kernel<<<C2, 256>>>(p2s, p2q, bn2_g, bn2_b, s2, t2);
    fold2h_kernel<<<C3, 128>>>(w2, b2, s2, t2, w2h, b2f);
    gemm2_f16_kernel<<<dim3(16, 1, 32), 256>>>(w2h, h, b2f, out);
}

// round 13
// speedup vs baseline: 1.9753x; 1.0198x over previous
#include <cuda_runtime.h>
#include <cuda_fp16.h>
#include <cstdint>
#include <cstddef>

// ---------------------------------------------------------------------------
// Bottleneck: BN -> conv1x1(1024->256) -> relu -> BN -> conv1x1(256->64)
// B=32, C=1024, T=2048.  BN folded into GEMM weights.
// x materialized once to fp16 inside bn1-stats; both GEMMs are fp16
// mma.sync m16n8k16 with cp.async global->SMEM tiles and ldmatrix fragment
// loads.  GEMM1 uses a 3-stage cp.async pipeline with ONE barrier per
// k-iteration.  h kept in fp16.  BN2 stats fused into GEMM1 epilogue.
// ---------------------------------------------------------------------------

#define EPSV 1e-5f
constexpr int Tdim = 2048;
constexpr int Bn   = 32;
constexpr int C1 = 1024, C2 = 256, C3 = 64;

// scratch (allocation-free rule: __device__ globals)
__device__ __half   g_xh[(size_t)Bn * C1 * Tdim];  // 128 MiB x in fp16
__device__ __half   g_h[(size_t)Bn * C2 * Tdim];   // 32 MiB intermediate fp16
__device__ float    g_p1s[8 * C1], g_p1q[8 * C1];  // stats1 partials
__device__ float    g_s1[C1], g_t1[C1];
__device__ uint32_t g_w1h[C2 * (C1 / 2)];          // folded W1, half2 k-pairs
__device__ float    g_b1f[C2];
__device__ float    g_p2s[2 * 16 * 32 * 128];      // per-CTA BN2 partials
__device__ float    g_p2q[2 * 16 * 32 * 128];
__device__ float    g_s2[C2], g_t2[C2];
__device__ uint32_t g_w2h[C3 * (C2 / 2)];          // folded W2, half2 k-pairs
__device__ float    g_b2f[C3];

// ---------------------------------------------------------------------------
// helpers
// ---------------------------------------------------------------------------
__device__ __forceinline__ uint32_t pack_h2(float lo, float hi) {
    __half2 h = __floats2half2_rn(lo, hi);
    return *reinterpret_cast<uint32_t*>(&h);
}

__device__ __forceinline__ uint32_t smem_u32(const void* p) {
    uint32_t a;
    asm("{ .reg .u64 t; cvta.to.shared.u64 t, %1; cvt.u32.u64 %0, t; }"
        : "=r"(a) : "l"(p));
    return a;
}

__device__ __forceinline__ void mma16(float* c, const uint32_t* a, const uint32_t* b) {
    asm volatile(
        "mma.sync.aligned.m16n8k16.row.col.f32.f16.f16.f32 "
        "{%0,%1,%2,%3}, {%4,%5,%6,%7}, {%8,%9}, {%0,%1,%2,%3};"
        : "+f"(c[0]), "+f"(c[1]), "+f"(c[2]), "+f"(c[3])
        : "r"(a[0]), "r"(a[1]), "r"(a[2]), "r"(a[3]), "r"(b[0]), "r"(b[1]));
}

#define CP16(dst, src) \
    asm volatile("cp.async.cg.shared.global [%0], [%1], 16;" \
                 :: "r"(dst), "l"(src) : "memory")
#define CP_COMMIT()  asm volatile("cp.async.commit_group;" ::: "memory")
#define CP_WAIT0()   asm volatile("cp.async.wait_group 0;" ::: "memory")
#define CP_WAIT1()   asm volatile("cp.async.wait_group 1;" ::: "memory")

#define LDSM4(r0, r1, r2, r3, a) \
    asm volatile("ldmatrix.sync.aligned.m8n8.x4.shared.b16 {%0,%1,%2,%3}, [%4];" \
                 : "=r"(r0), "=r"(r1), "=r"(r2), "=r"(r3) : "r"(a))
#define LDSM4T(r0, r1, r2, r3, a) \
    asm volatile("ldmatrix.sync.aligned.m8n8.x4.trans.shared.b16 {%0,%1,%2,%3}, [%4];" \
                 : "=r"(r0), "=r"(r1), "=r"(r2), "=r"(r3) : "r"(a))

// SMEM geometry shared by both GEMMs
constexpr int AS_STRIDE = 80;              // A row: 32 halves + 8 pad (bytes)
constexpr int BS_STRIDE = 272;             // B row: 128 halves + 8 pad (bytes)
constexpr int BS_BUF    = 32 * BS_STRIDE;  // 8704 B per buffer

// ---------------------------------------------------------------------------
// BN1 stats (8-way batch split) + fp16 materialization of x.
// ---------------------------------------------------------------------------
__global__ void bn1_part_kernel(const float* __restrict__ x,
                                float* __restrict__ ps, float* __restrict__ pq,
                                __half* __restrict__ xh)
{
    const int c = blockIdx.x, q = blockIdx.y, tid = threadIdx.x;
    float s = 0.f, ss = 0.f;
    const size_t cstride = (size_t)C1 * Tdim;
#pragma unroll
    for (int bb = 0; bb < 4; ++bb) {
        const size_t rowoff = (size_t)(q * 4 + bb) * cstride + (size_t)c * Tdim;
        const float4* row = reinterpret_cast<const float4*>(x + rowoff);
        float4 v0 = row[tid * 2];
        float4 v1 = row[tid * 2 + 1];
        s  += (v0.x + v0.y) + (v0.z + v0.w) + (v1.x + v1.y) + (v1.z + v1.w);
        ss += (v0.x * v0.x + v0.y * v0.y) + (v0.z * v0.z + v0.w * v0.w)
            + (v1.x * v1.x + v1.y * v1.y) + (v1.z * v1.z + v1.w * v1.w);
        uint4 o4;
        o4.x = pack_h2(v0.x, v0.y); o4.y = pack_h2(v0.z, v0.w);
        o4.z = pack_h2(v1.x, v1.y); o4.w = pack_h2(v1.z, v1.w);
        *reinterpret_cast<uint4*>(xh + rowoff + tid * 8) = o4;
    }
#pragma unroll
    for (int o = 16; o > 0; o >>= 1) {
        s  += __shfl_xor_sync(0xffffffffu, s, o);
        ss += __shfl_xor_sync(0xffffffffu, ss, o);
    }
    __shared__ float rs[8], rss[8];
    if ((tid & 31) == 0) { rs[tid >> 5] = s; rss[tid >> 5] = ss; }
    __syncthreads();
    if (tid == 0) {
        float S = 0.f, SS = 0.f;
#pragma unroll
        for (int i = 0; i < 8; ++i) { S += rs[i]; SS += rss[i]; }
        ps[q * C1 + c] = S;
        pq[q * C1 + c] = SS;
    }
}

__global__ void finalize1_kernel(const float* __restrict__ ps,
                                 const float* __restrict__ pq,
                                 const float* __restrict__ gamma,
                                 const float* __restrict__ beta,
                                 float* __restrict__ s_out,
                                 float* __restrict__ t_out)
{
    int c = blockIdx.x * 256 + threadIdx.x;
    float S = 0.f, SS = 0.f;
#pragma unroll
    for (int q = 0; q < 8; ++q) { S += ps[q * C1 + c]; SS += pq[q * C1 + c]; }
    const float invN = 1.0f / (float)(Bn * Tdim);
    float mean = S * invN;
    float var  = SS * invN - mean * mean;
    float sc   = gamma[c] * rsqrtf(var + EPSV);
    s_out[c] = sc;
    t_out[c] = beta[c] - mean * sc;
}

// ---------------------------------------------------------------------------
// Fold BN1 into W1; emit packed half2 (k-pairs) + fp32 bias.
// ---------------------------------------------------------------------------
__global__ void fold1h_kernel(const float* __restrict__ w,
                              const float* __restrict__ bias_in,
                              const float* __restrict__ s,
                              const float* __restrict__ t,
                              uint32_t* __restrict__ wh,
                              float* __restrict__ bf)
{
    const int o = blockIdx.x, tid = threadIdx.x;
    float part = 0.f;
    for (int c2 = tid; c2 < C1 / 2; c2 += 256) {
        float w0 = w[(size_t)o * C1 + 2 * c2];
        float w1 = w[(size_t)o * C1 + 2 * c2 + 1];
        part += w0 * t[2 * c2] + w1 * t[2 * c2 + 1];
        wh[(size_t)o * (C1 / 2) + c2] = pack_h2(w0 * s[2 * c2], w1 * s[2 * c2 + 1]);
    }
#pragma unroll
    for (int off = 16; off > 0; off >>= 1)
        part += __shfl_xor_sync(0xffffffffu, part, off);
    __shared__ float red[8];
    if ((tid & 31) == 0) red[tid >> 5] = part;
    __syncthreads();
    if (tid == 0) {
        float tot = 0.f;
#pragma unroll
        for (int i = 0; i < 8; ++i) tot += red[i];
        bf[o] = bias_in[o] + tot;
    }
}

// Fold BN2 into W2 (half2 pairs).  64 blocks x 128 threads.
__global__ void fold2h_kernel(const float* __restrict__ w,
                              const float* __restrict__ bias_in,
                              const float* __restrict__ s,
                              const float* __restrict__ t,
                              uint32_t* __restrict__ wh,
                              float* __restrict__ bf)
{
    const int o = blockIdx.x, tid = threadIdx.x;   // tid = c2, 0..127
    float w0 = w[(size_t)o * C2 + 2 * tid];
    float w1 = w[(size_t)o * C2 + 2 * tid + 1];
    float part = w0 * t[2 * tid] + w1 * t[2 * tid + 1];
    wh[(size_t)o * (C2 / 2) + tid] = pack_h2(w0 * s[2 * tid], w1 * s[2 * tid + 1]);
#pragma unroll
    for (int off = 16; off > 0; off >>= 1)
        part += __shfl_xor_sync(0xffffffffu, part, off);
    __shared__ float red[4];
    if ((tid & 31) == 0) red[tid >> 5] = part;
    __syncthreads();
    if (tid == 0)
        bf[o] = bias_in[o] + red[0] + red[1] + red[2] + red[3];
}

// ---------------------------------------------------------------------------
// GEMM1 fp16: h[b,o,t] = relu( sum_k W[o,k]*X[b,k,t] + bias[o] )   (fp16 out)
// Block 128(o) x 128(t), BK=32, 8 warps (2x4), warp tile 64x32.
// 3-stage cp.async pipeline, ONE __syncthreads per k-iteration.
// Epilogue: bias+relu, fp16 h store, deterministic per-CTA BN2 partials
// (sstat aliases the dead pipeline SMEM).
// ---------------------------------------------------------------------------
constexpr int AS1_BUF  = 128 * AS_STRIDE;            // 10240 B per stage
constexpr int NST      = 3;
constexpr int G1_SMEM  = NST * (AS1_BUF + BS_BUF);   // 56832 B

__global__ __launch_bounds__(256, 2)
void gemm1_f16_kernel(const uint32_t* __restrict__ Ah,
                      const __half* __restrict__ Xh,
                      const float* __restrict__ bias,
                      __half* __restrict__ H,
                      float* __restrict__ part_s, float* __restrict__ part_q)
{
    extern __shared__ __align__(16) char dynsm[];
    const uint32_t as0 = smem_u32(dynsm);                    // 3 A stages
    const uint32_t bs0 = as0 + NST * AS1_BUF;                // 3 B stages

    const int tid = threadIdx.x, wid = tid >> 5, lane = tid & 31;
    const int wrow = wid >> 2, wcol = wid & 3;
    const int gid  = lane >> 2, tig = lane & 3;
    const int b  = blockIdx.z;
    const int t0 = blockIdx.x * 128;
    const int m0 = blockIdx.y * 128;

    float acc[4][4][4];
#pragma unroll
    for (int i = 0; i < 4; ++i)
#pragma unroll
        for (int j = 0; j < 4; ++j)
#pragma unroll
            for (int e = 0; e < 4; ++e) acc[i][j][e] = 0.f;

    auto issue = [&](int kt, int buf) {
        const uint32_t ab = as0 + buf * AS1_BUF;
        const uint32_t bb = bs0 + buf * BS_BUF;
#pragma unroll
        for (int i = 0; i < 2; ++i) {
            const int u = tid * 2 + i;
            const int o = u >> 2, j = u & 3;           // A: 128 rows x 4 chunks
            CP16(ab + o * AS_STRIDE + j * 16,
                 (const char*)Ah + (size_t)(m0 + o) * 2048 + kt * 64 + j * 16);
            const int k = u >> 4, c = u & 15;          // B: 32 rows x 16 chunks
            CP16(bb + k * BS_STRIDE + c * 16,
                 (const char*)Xh +
                 (((size_t)b * C1 + kt * 32 + k) * Tdim + t0 + c * 8) * 2);
        }
        CP_COMMIT();
    };

    // prologue: 2 stages in flight
    issue(0, 0);
    issue(1, 1);

    for (int kt = 0; kt < 32; ++kt) {
        if (kt < 31) CP_WAIT1(); else CP_WAIT0();      // stage kt landed
        __syncthreads();                               // all warps past kt-1
        if (kt + 2 < 32) issue(kt + 2, (kt + 2) % NST);

        const uint32_t ab = as0 + (kt % NST) * AS1_BUF;
        const uint32_t bb = bs0 + (kt % NST) * BS_BUF;
        const int g = lane >> 3;
        const int krow = ((g & 1) << 3) + (lane & 7);
        const int ncol = (g >> 1) << 3;
#pragma unroll
        for (int kc = 0; kc < 2; ++kc) {
            uint32_t af[4][4], bf[4][2];
#pragma unroll
            for (int mt = 0; mt < 4; ++mt) {
                uint32_t addr = ab + (wrow * 64 + mt * 16 + (lane & 15)) * AS_STRIDE
                              + kc * 32 + ((lane >> 4) << 4);
                LDSM4(af[mt][0], af[mt][1], af[mt][2], af[mt][3], addr);
            }
#pragma unroll
            for (int pr = 0; pr < 2; ++pr) {
                uint32_t addr = bb + (kc * 16 + krow) * BS_STRIDE
                              + (wcol * 32 + pr * 16 + ncol) * 2;
                LDSM4T(bf[pr * 2][0], bf[pr * 2][1],
                       bf[pr * 2 + 1][0], bf[pr * 2 + 1][1], addr);
            }
#pragma unroll
            for (int mt = 0; mt < 4; ++mt)
#pragma unroll
                for (int nt = 0; nt < 4; ++nt)
                    mma16(acc[mt][nt], af[mt], bf[nt]);
        }
        // no trailing barrier: next iteration's top barrier protects reuse
    }
    __syncthreads();                                   // before SMEM reuse

    // ---- epilogue: bias + relu + fp16 h store + deterministic BN2 partials
    float (*sstat)[128][2] = reinterpret_cast<float(*)[128][2]>(dynsm);
#pragma unroll
    for (int mt = 0; mt < 4; ++mt) {
        const int row_l = wrow * 64 + mt * 16 + gid;
        const int row   = m0 + row_l;
        const float bz0 = bias[row];
        const float bz1 = bias[row + 8];
        float rsum0 = 0.f, rss0 = 0.f, rsum1 = 0.f, rss1 = 0.f;
#pragma unroll
        for (int nt = 0; nt < 4; ++nt) {
            const int col = t0 + wcol * 32 + nt * 8 + tig * 2;
            float v00 = fmaxf(acc[mt][nt][0] + bz0, 0.f);
            float v01 = fmaxf(acc[mt][nt][1] + bz0, 0.f);
            float v10 = fmaxf(acc[mt][nt][2] + bz1, 0.f);
            float v11 = fmaxf(acc[mt][nt][3] + bz1, 0.f);
            *reinterpret_cast<__half2*>(H + ((size_t)b * C2 + row) * Tdim + col)
                = __floats2half2_rn(v00, v01);
            *reinterpret_cast<__half2*>(H + ((size_t)b * C2 + row + 8) * Tdim + col)
                = __floats2half2_rn(v10, v11);
            rsum0 += v00 + v01;  rss0 += v00 * v00 + v01 * v01;
            rsum1 += v10 + v11;  rss1 += v10 * v10 + v11 * v11;
        }
#pragma unroll
        for (int o = 1; o < 4; o <<= 1) {
            rsum0 += __shfl_xor_sync(0xffffffffu, rsum0, o);
            rss0  += __shfl_xor_sync(0xffffffffu, rss0,  o);
            rsum1 += __shfl_xor_sync(0xffffffffu, rsum1, o);
            rss1  += __shfl_xor_sync(0xffffffffu, rss1,  o);
        }
        if (tig == 0) {
            sstat[wcol][row_l][0]     = rsum0;
            sstat[wcol][row_l][1]     = rss0;
            sstat[wcol][row_l + 8][0] = rsum1;
            sstat[wcol][row_l + 8][1] = rss1;
        }
    }
    __syncthreads();
    if (tid < 128) {
        float S  = sstat[0][tid][0] + sstat[1][tid][0]
                 + sstat[2][tid][0] + sstat[3][tid][0];
        float SS = sstat[0][tid][1] + sstat[1][tid][1]
                 + sstat[2][tid][1] + sstat[3][tid][1];
        const int cbase = (((blockIdx.y * 16 + blockIdx.x) * 32 + blockIdx.z) << 7);
        part_s[cbase + tid] = S;
        part_q[cbase + tid] = SS;
    }
}

// finalize BN2 scale/shift from per-CTA partials (deterministic)
__global__ void finalize2_kernel(const float* __restrict__ ps,
                                 const float* __restrict__ pq,
                                 const float* __restrict__ gamma,
                                 const float* __restrict__ beta,
                                 float* __restrict__ s_out,
                                 float* __restrict__ t_out)
{
    const int o = blockIdx.x;
    const int mtile = o >> 7, row = o & 127;
    const int tid = threadIdx.x;
    float S = 0.f, SS = 0.f;
    for (int i = tid; i < 512; i += 256) {
        int idx = ((mtile * 512 + i) << 7) + row;
        S += ps[idx]; SS += pq[idx];
    }
#pragma unroll
    for (int off = 16; off > 0; off >>= 1) {
        S  += __shfl_xor_sync(0xffffffffu, S, off);
        SS += __shfl_xor_sync(0xffffffffu, SS, off);
    }
    __shared__ float rs[8], rss[8];
    if ((tid & 31) == 0) { rs[tid >> 5] = S; rss[tid >> 5] = SS; }
    __syncthreads();
    if (tid == 0) {
        float T = 0.f, TT = 0.f;
#pragma unroll
        for (int i = 0; i < 8; ++i) { T += rs[i]; TT += rss[i]; }
        const float invN = 1.0f / (float)(Bn * Tdim);
        float mean = T * invN;
        float var  = TT * invN - mean * mean;
        float sc   = gamma[o] * rsqrtf(var + EPSV);
        s_out[o] = sc;
        t_out[o] = beta[o] - mean * sc;
    }
}

// ---------------------------------------------------------------------------
// GEMM2 fp16: out = W2f @ h + b2f, mu/logvar scatter (fp32 out).
// Block 64(o) x 128(t), BK=32, 8 warps (2x4), warp tile 32x32, K=256.
// ---------------------------------------------------------------------------
constexpr int AS2_BUF = 64 * AS_STRIDE;    // 5120 B per buffer

__global__ __launch_bounds__(256, 2)
void gemm2_f16_kernel(const uint32_t* __restrict__ Ah,
                      const __half* __restrict__ Hh,
                      const float* __restrict__ bias,
                      float* __restrict__ Out)
{
    __shared__ __align__(16) char Asm[2 * AS2_BUF];
    __shared__ __align__(16) char Bsm[2 * BS_BUF];

    const int tid = threadIdx.x, wid = tid >> 5, lane = tid & 31;
    const int wrow = wid >> 2, wcol = wid & 3;
    const int gid  = lane >> 2, tig = lane & 3;
    const int b  = blockIdx.z;
    const int t0 = blockIdx.x * 128;

    const uint32_t as0 = smem_u32(Asm), bs0 = smem_u32(Bsm);

    float acc[2][4][4];
#pragma unroll
    for (int i = 0; i < 2; ++i)
#pragma unroll
        for (int j = 0; j < 4; ++j)
#pragma unroll
            for (int e = 0; e < 4; ++e) acc[i][j][e] = 0.f;

    auto issue = [&](int kt, int buf) {
        const uint32_t ab = as0 + buf * AS2_BUF;
        const uint32_t bb = bs0 + buf * BS_BUF;
        {   // A: 64 rows x 4 chunks = 256, 1 per thread
            const int o = tid >> 2, j = tid & 3;
            CP16(ab + o * AS_STRIDE + j * 16,
                 (const char*)Ah + (size_t)o * 512 + kt * 64 + j * 16);
        }
#pragma unroll
        for (int i = 0; i < 2; ++i) {                  // B: 512, 2 per thread
            const int u = tid * 2 + i;
            const int k = u >> 4, c = u & 15;
            CP16(bb + k * BS_STRIDE + c * 16,
                 (const char*)Hh +
                 (((size_t)b * C2 + kt * 32 + k) * Tdim + t0 + c * 8) * 2);
        }
        CP_COMMIT();
    };

    issue(0, 0);
    for (int kt = 0; kt < 8; ++kt) {
        const int cur = kt & 1;
        if (kt + 1 < 8) { issue(kt + 1, cur ^ 1); CP_WAIT1(); }
        else            { CP_WAIT0(); }
        __syncthreads();

        const uint32_t ab = as0 + cur * AS2_BUF;
        const uint32_t bb = bs0 + cur * BS_BUF;
        const int g = lane >> 3;
        const int krow = ((g & 1) << 3) + (lane & 7);
        const int ncol = (g >> 1) << 3;
#pragma unroll
        for (int kc = 0; kc < 2; ++kc) {
            uint32_t af[2][4], bf[4][2];
#pragma unroll
            for (int mt = 0; mt < 2; ++mt) {
                uint32_t addr = ab + (wrow * 32 + mt * 16 + (lane & 15)) * AS_STRIDE
                              + kc * 32 + ((lane >> 4) << 4);
                LDSM4(af[mt][0], af[mt][1], af[mt][2], af[mt][3], addr);
            }
#pragma unroll
            for (int pr = 0; pr < 2; ++pr) {
                uint32_t addr = bb + (kc * 16 + krow) * BS_STRIDE
                              + (wcol * 32 + pr * 16 + ncol) * 2;
                LDSM4T(bf[pr * 2][0], bf[pr * 2][1],
                       bf[pr * 2 + 1][0], bf[pr * 2 + 1][1], addr);
            }
#pragma unroll
            for (int mt = 0; mt < 2; ++mt)
#pragma unroll
                for (int nt = 0; nt < 4; ++nt)
                    mma16(acc[mt][nt], af[mt], bf[nt]);
        }
        __syncthreads();
    }

    // epilogue: bias + mu/logvar scatter (fp32 out)
#pragma unroll
    for (int mt = 0; mt < 2; ++mt) {
        const int row = wrow * 32 + mt * 16 + gid;
        const float bz0 = bias[row];
        const float bz1 = bias[row + 8];
#pragma unroll
        for (int nt = 0; nt < 4; ++nt) {
            const int col = t0 + wcol * 32 + nt * 8 + tig * 2;
            const int row1 = row + 8;
            size_t i0 = (row < 32)
                ? ((size_t)b * 65536 + (size_t)row * Tdim)
                : (2097152 + (size_t)b * 65536 + (size_t)(row - 32) * Tdim);
            size_t i1 = (row1 < 32)
                ? ((size_t)b * 65536 + (size_t)row1 * Tdim)
                : (2097152 + (size_t)b * 65536 + (size_t)(row1 - 32) * Tdim);
            float2 v0 = make_float2(acc[mt][nt][0] + bz0, acc[mt][nt][1] + bz0);
            float2 v1 = make_float2(acc[mt][nt][2] + bz1, acc[mt][nt][3] + bz1);
            *reinterpret_cast<float2*>(Out + i0 + col) = v0;
            *reinterpret_cast<float2*>(Out + i1 + col) = v1;
        }
    }
}

// ---------------------------------------------------------------------------
extern "C" void kernel_launch(void* const* d_in, const int* in_sizes, int n_in,
                              void* d_out, int out_size)
{
    const float* x     = (const float*)d_in[0];
    const float* bn1_g = (const float*)d_in[1];
    const float* bn1_b = (const float*)d_in[2];
    const float* w1    = (const float*)d_in[3];
    const float* b1    = (const float*)d_in[4];
    const float* bn2_g = (const float*)d_in[5];
    const float* bn2_b = (const float*)d_in[6];
    const float* w2    = (const float*)d_in[7];
    const float* b2    = (const float*)d_in[8];
    float* out = (float*)d_out;

    __half *xh, *h;
    float *p1s, *p1q, *s1, *t1, *b1f, *p2s, *p2q, *s2, *t2, *b2f;
    uint32_t *w1h, *w2h;
    cudaGetSymbolAddress((void**)&xh,  g_xh);
    cudaGetSymbolAddress((void**)&h,   g_h);
    cudaGetSymbolAddress((void**)&p1s, g_p1s);
    cudaGetSymbolAddress((void**)&p1q, g_p1q);
    cudaGetSymbolAddress((void**)&s1,  g_s1);
    cudaGetSymbolAddress((void**)&t1,  g_t1);
    cudaGetSymbolAddress((void**)&w1h, g_w1h);
    cudaGetSymbolAddress((void**)&b1f, g_b1f);
    cudaGetSymbolAddress((void**)&p2s, g_p2s);
    cudaGetSymbolAddress((void**)&p2q, g_p2q);
    cudaGetSymbolAddress((void**)&s2,  g_s2);
    cudaGetSymbolAddress((void**)&t2,  g_t2);
    cudaGetSymbolAddress((void**)&w2h, g_w2h);
    cudaGetSymbolAddress((void**)&b2f, g_b2f);

    cudaFuncSetAttribute(gemm1_f16_kernel,
                         cudaFuncAttributeMaxDynamicSharedMemorySize, G1_SMEM);

    // BN1 stats + x->fp16 materialization -> scale/shift -> fold W1 (fp16)
    bn1_part_kernel<<<dim3(C1, 8), 256>>>(x, p1s, p1q, xh);
    finalize1_kernel<<<4, 256>>>(p1s, p1q, bn1_g, bn1_b, s1, t1);
    fold1h_kernel<<<C2, 256>>>(w1, b1, s1, t1, w1h, b1f);

    // GEMM1 fp16 (3-stage cp.async + ldmatrix) with fused BN2 partial stats
    gemm1_f16_kernel<<<dim3(16, 2, 32), 256, G1_SMEM>>>(w1h, xh, b1f, h, p2s, p2q);

    // finalize BN2 -> fold W2 (fp16) -> GEMM2 fp16 with mu/logvar scatter
    finalize2_kernel<<<C2, 256>>>(p2s, p2q, bn2_g, bn2_b, s2, t2);
    fold2h_kernel<<<C3, 128>>>(w2, b2, s2, t2, w2h, b2f);
    gemm2_f16_kernel<<<dim3(16, 1, 32), 256>>>(w2h, h, b2f, out);
}